// round 4
// baseline (speedup 1.0000x reference)
#include <cuda_runtime.h>
#include <cstdint>

// Problem constants
#define B_SZ 4096   // batch
#define NI   256    // raw input dim (per side)
#define NA   257    // augmented dim (input + 1)
#define NN   256    // neurons

// Kernel-1 tiling
#define BM   64     // batch rows per CTA
#define BN   64     // output cols per CTA
#define JC   32     // j-chunk (K inner tile)
#define TM   8      // rows per thread
#define TN   8      // cols per thread
#define NTHR 64     // 8 tx * 8 ty
#define BSTR 36     // b_s row stride in floats (16B-aligned rows)
#define WSTR 64     // w_s row stride in floats

// Hidden activations scratch (device global: no allocation allowed)
__device__ float g_h[B_SZ * NN];

// ---------- packed f32x2 helpers (FFMA2 path; 2x fp32 throughput on sm_103a) ----
static __device__ __forceinline__ unsigned long long pk1(float x) {
    unsigned long long r;
    asm("mov.b64 %0, {%1, %1};" : "=l"(r) : "f"(x));
    return r;
}
static __device__ __forceinline__ unsigned long long ffma2(
    unsigned long long a, unsigned long long b, unsigned long long c) {
    unsigned long long d;
    asm("fma.rn.f32x2 %0, %1, %2, %3;" : "=l"(d) : "l"(a), "l"(b), "l"(c));
    return d;
}
static __device__ __forceinline__ void upk(unsigned long long v, float& x, float& y) {
    asm("mov.b64 {%0, %1}, %2;" : "=f"(x), "=f"(y) : "l"(v));
}
union F4U { float4 f; unsigned long long u[2]; };

// ---------- cp.async helpers ----------------------------------------------------
static __device__ __forceinline__ void cp16(void* s, const void* g) {
    unsigned int sa = (unsigned int)__cvta_generic_to_shared(s);
    asm volatile("cp.async.cg.shared.global [%0], [%1], 16;" :: "r"(sa), "l"(g));
}
static __device__ __forceinline__ void cpcommit() {
    asm volatile("cp.async.commit_group;");
}
template <int N>
static __device__ __forceinline__ void cpwait() {
    asm volatile("cp.async.wait_group %0;" :: "n"(N));
}

// ---------- chunk loader: W1 tile [JC x BN] + b tile [BM x JC] ------------------
static __device__ __forceinline__ void load_chunk(
    int c, int buf, int m0, int n0,
    const float* __restrict__ inp2, const float* __restrict__ W1,
    float* __restrict__ b_s, float* __restrict__ w_s, int tid) {
    const int i  = c >> 3;          // a-column index (fixed per 8 chunks)
    const int jc = (c & 7) * JC;    // j offset within [0,256)

    // W1 rows k = i*257 + jc + row, row in [0,32): 512 float4, 8 per thread
    const float* wg = W1 + ((size_t)i * NA + jc) * NN + n0;
    float* wbuf = w_s + buf * (JC * WSTR);
#pragma unroll
    for (int q = 0; q < 8; q++) {
        int e = tid + q * NTHR;
        int row = e >> 4;           // 16 float4 per 64-float row
        int c4  = e & 15;
        cp16(&wbuf[row * WSTR + c4 * 4], wg + (size_t)row * NN + c4 * 4);
    }

    // b tile: inp2[m0+row][jc .. jc+31]: 512 float4, 8 per thread
    const float* bg = inp2 + (size_t)m0 * NI + jc;
    float* bbuf = b_s + buf * (BM * BSTR);
#pragma unroll
    for (int q = 0; q < 8; q++) {
        int e = tid + q * NTHR;
        int row = e >> 3;           // 8 float4 per 32-float row
        int c4  = e & 7;
        cp16(&bbuf[row * BSTR + c4 * 4], bg + (size_t)row * NI + c4 * 4);
    }
    cpcommit();
}

// =================================================================================
// Kernel 1: h = relu( fusion(inp1,inp2) @ W1 + b1 )
//   fusion[m, i*257+j] = a[m,i]*b[m,j],  a=[inp1,1], b=[inp2,1]
//   For fixed i: A[m,j] = p[m]*b[m,j] with p[m]=a[m,i]  -> generated on the fly.
// =================================================================================
__global__ void __launch_bounds__(NTHR) outer_fused_l1(
    const float* __restrict__ inp1, const float* __restrict__ inp2,
    const float* __restrict__ W1, const float* __restrict__ b1) {
    __shared__ float b_s[2 * BM * BSTR];   // 18 KB
    __shared__ float w_s[2 * JC * WSTR];   // 16 KB

    const int tid = threadIdx.x;
    const int tx  = tid & 7;    // -> n
    const int ty  = tid >> 3;   // -> m
    const int m0  = blockIdx.y * BM;
    const int n0  = blockIdx.x * BN;

    unsigned long long acc[TM][TN / 2];
#pragma unroll
    for (int mm = 0; mm < TM; mm++)
#pragma unroll
        for (int q = 0; q < TN / 2; q++) acc[mm][q] = 0ull;  // (0.f,0.f)

    float p[TM];
    F4U tw0, tw1;  // tail row (j == 256) of W1 for current i

    load_chunk(0, 0, m0, n0, inp2, W1, b_s, w_s, tid);

    const int C = NA * 8;  // 257 i-blocks * 8 chunks
    int buf = 0;
    for (int c = 0; c < C; ++c) {
        // issue next chunk's async copies into the other buffer
        if (c + 1 < C)
            load_chunk(c + 1, buf ^ 1, m0, n0, inp2, W1, b_s, w_s, tid);

        // per-i scalars and tail row: issue early so latency overlaps the wait
        if ((c & 7) == 0) {
            const int i = c >> 3;
#pragma unroll
            for (int mm = 0; mm < TM; mm++)
                p[mm] = (i < NI)
                    ? __ldg(inp1 + (size_t)(m0 + ty * TM + mm) * NI + i)
                    : 1.0f;
            const float* tg = W1 + ((size_t)i * NA + 256) * NN + n0 + tx * TN;
            tw0.f = *(const float4*)tg;
            tw1.f = *(const float4*)(tg + 4);
        }

        if (c + 1 < C) cpwait<1>(); else cpwait<0>();
        __syncthreads();

        const float* bbuf = b_s + buf * (BM * BSTR);
        const float* wbuf = w_s + buf * (JC * WSTR);

#pragma unroll 2
        for (int jj = 0; jj < JC; jj += 4) {
            F4U bq[TM];
#pragma unroll
            for (int mm = 0; mm < TM; mm++)
                bq[mm].f = *(const float4*)&bbuf[(ty * TM + mm) * BSTR + jj];
#pragma unroll
            for (int t = 0; t < 4; t++) {
                F4U w0, w1;
                w0.f = *(const float4*)&wbuf[(jj + t) * WSTR + tx * TN];
                w1.f = *(const float4*)&wbuf[(jj + t) * WSTR + tx * TN + 4];
#pragma unroll
                for (int mm = 0; mm < TM; mm++) {
                    const float bv = ((const float*)&bq[mm].f)[t];
                    const unsigned long long av = pk1(p[mm] * bv);
                    acc[mm][0] = ffma2(av, w0.u[0], acc[mm][0]);
                    acc[mm][1] = ffma2(av, w0.u[1], acc[mm][1]);
                    acc[mm][2] = ffma2(av, w1.u[0], acc[mm][2]);
                    acc[mm][3] = ffma2(av, w1.u[1], acc[mm][3]);
                }
            }
        }

        // tail j == 256 for this i: b = 1 -> A = p[m]
        if ((c & 7) == 7) {
#pragma unroll
            for (int mm = 0; mm < TM; mm++) {
                const unsigned long long av = pk1(p[mm]);
                acc[mm][0] = ffma2(av, tw0.u[0], acc[mm][0]);
                acc[mm][1] = ffma2(av, tw0.u[1], acc[mm][1]);
                acc[mm][2] = ffma2(av, tw1.u[0], acc[mm][2]);
                acc[mm][3] = ffma2(av, tw1.u[1], acc[mm][3]);
            }
        }

        buf ^= 1;
        __syncthreads();
    }

    // epilogue: + b1, relu, store h
#pragma unroll
    for (int mm = 0; mm < TM; mm++) {
        const int gm = m0 + ty * TM + mm;
        float* hp = g_h + (size_t)gm * NN + n0 + tx * TN;
#pragma unroll
        for (int q = 0; q < TN / 2; q++) {
            float x, y;
            upk(acc[mm][q], x, y);
            const int n = n0 + tx * TN + q * 2;
            x = fmaxf(x + __ldg(b1 + n),     0.0f);
            y = fmaxf(y + __ldg(b1 + n + 1), 0.0f);
            hp[q * 2]     = x;
            hp[q * 2 + 1] = y;
        }
    }
}

// =================================================================================
// Kernel 2: out = relu( h @ W2 + b2 )   [4096x256]@[256x256] -- tiny (0.5 GF)
// =================================================================================
#define K2_BM 16
__global__ void __launch_bounds__(256) outer_fused_l2(
    const float* __restrict__ W2, const float* __restrict__ b2,
    float* __restrict__ out) {
    __shared__ float h_s[K2_BM][NN];
    const int m0  = blockIdx.x * K2_BM;
    const int tid = threadIdx.x;

    // load h tile [16 x 256]: 1024 float4, 4 per thread
#pragma unroll
    for (int q = 0; q < 4; q++) {
        int e = tid + q * 256;
        int row = e >> 6;
        int c4  = e & 63;
        *(float4*)&h_s[row][c4 * 4] =
            *(const float4*)(g_h + (size_t)(m0 + row) * NN + c4 * 4);
    }
    __syncthreads();

    float acc[K2_BM];
#pragma unroll
    for (int mm = 0; mm < K2_BM; mm++) acc[mm] = 0.0f;

    const int n = tid;
#pragma unroll 4
    for (int k = 0; k < NN; k++) {
        const float w = __ldg(W2 + (size_t)k * NN + n);
#pragma unroll
        for (int mm = 0; mm < K2_BM; mm++)
            acc[mm] = fmaf(h_s[mm][k], w, acc[mm]);
    }

    const float bb = __ldg(b2 + n);
#pragma unroll
    for (int mm = 0; mm < K2_BM; mm++)
        out[(size_t)(m0 + mm) * NN + n] = fmaxf(acc[mm] + bb, 0.0f);
}

// =================================================================================
extern "C" void kernel_launch(void* const* d_in, const int* in_sizes, int n_in,
                              void* d_out, int out_size) {
    const float* inp1 = (const float*)d_in[0];  // [4096, 256]
    const float* inp2 = (const float*)d_in[1];  // [4096, 256]
    const float* W1   = (const float*)d_in[2];  // [66049, 256]
    const float* b1   = (const float*)d_in[3];  // [256]
    const float* W2   = (const float*)d_in[4];  // [256, 256]
    const float* b2   = (const float*)d_in[5];  // [256]
    float* out = (float*)d_out;                 // [4096, 256]

    dim3 g1(NN / BN, B_SZ / BM);  // (4, 64) = 256 CTAs
    outer_fused_l1<<<g1, NTHR>>>(inp1, inp2, W1, b1);
    outer_fused_l2<<<B_SZ / K2_BM, 256>>>(W2, b2, out);
}

// round 6
// speedup vs baseline: 3.4577x; 3.4577x over previous
#include <cuda_runtime.h>
#include <cstdint>

#define B_SZ   4096
#define NN     256
#define NA     257
#define KP2    67584        // W1t row length: 256 i-blocks * 264
#define NSPLIT 8
#define NSLOT  9            // 8 mma splits + 1 edge slot

// ---------------- device-global scratch (no allocation allowed) ----------------
__device__ __align__(256) float g_W1t[(size_t)NN * KP2];            // 69.2 MB
__device__ __align__(256) float g_aT [(size_t)256 * B_SZ];          // 4 MB
__device__ __align__(256) float g_bT [(size_t)256 * B_SZ];          // 4 MB
__device__ __align__(256) float g_part[(size_t)NSLOT * B_SZ * NN];  // 37.7 MB

// ---------------- helpers ----------------
static __device__ __forceinline__ uint32_t smem_u32(const void* p) {
    uint32_t a;
    asm("{ .reg .u64 t; cvta.to.shared.u64 t, %1; cvt.u32.u64 %0, t; }" : "=r"(a) : "l"(p));
    return a;
}
static __device__ __forceinline__ void cp16(uint32_t s, const void* g) {
    asm volatile("cp.async.cg.shared.global [%0], [%1], 16;" :: "r"(s), "l"(g));
}
static __device__ __forceinline__ uint32_t f2tf32(float x) {
    uint32_t u;
    asm("cvt.rna.tf32.f32 %0, %1;" : "=r"(u) : "f"(x));
    return u;
}
static __device__ __forceinline__ unsigned long long pk1(float x) {
    unsigned long long r;
    asm("mov.b64 %0, {%1, %1};" : "=l"(r) : "f"(x));
    return r;
}
static __device__ __forceinline__ unsigned long long ffma2(
    unsigned long long a, unsigned long long b, unsigned long long c) {
    unsigned long long d;
    asm("fma.rn.f32x2 %0, %1, %2, %3;" : "=l"(d) : "l"(a), "l"(b), "l"(c));
    return d;
}
static __device__ __forceinline__ void upk(unsigned long long v, float& x, float& y) {
    asm("mov.b64 {%0, %1}, %2;" : "=f"(x), "=f"(y) : "l"(v));
}
static __device__ __forceinline__ void ldsm4(uint32_t addr, uint32_t r[4]) {
    asm volatile("ldmatrix.sync.aligned.m8n8.x4.shared.b16 {%0,%1,%2,%3}, [%4];"
                 : "=r"(r[0]), "=r"(r[1]), "=r"(r[2]), "=r"(r[3]) : "r"(addr));
}
static __device__ __forceinline__ void mma_tf32(
    float d[4], const uint32_t a[4], const uint32_t b[2]) {
    asm volatile(
        "mma.sync.aligned.m16n8k8.row.col.f32.tf32.tf32.f32 "
        "{%0,%1,%2,%3}, {%4,%5,%6,%7}, {%8,%9}, {%0,%1,%2,%3};"
        : "+f"(d[0]), "+f"(d[1]), "+f"(d[2]), "+f"(d[3])
        : "r"(a[0]), "r"(a[1]), "r"(a[2]), "r"(a[3]), "r"(b[0]), "r"(b[1]));
}

// ================================================================================
// Pre-pass 1: transpose inp1 / inp2  ->  g_aT / g_bT
// ================================================================================
__global__ void __launch_bounds__(256) prep_inputs(
    const float* __restrict__ in1, const float* __restrict__ in2) {
    __shared__ float tile[32 * 33];
    const float* src = blockIdx.z ? in2 : in1;
    float* dst = blockIdx.z ? g_bT : g_aT;
    const int m0 = blockIdx.x * 32, c0 = blockIdx.y * 32;
    const int c = threadIdx.x & 31, r0 = threadIdx.x >> 5;
#pragma unroll
    for (int q = 0; q < 4; q++) {
        int r = r0 + q * 8;
        tile[c * 33 + r] = src[(size_t)(m0 + r) * 256 + c0 + c];
    }
    __syncthreads();
#pragma unroll
    for (int q = 0; q < 4; q++) {
        int rr = r0 + q * 8;
        dst[(size_t)(c0 + rr) * B_SZ + m0 + c] = tile[rr * 33 + c];
    }
}

// ================================================================================
// Pre-pass 2: W1t[n][i*264 + j] = tf32(W1[i*257+j][n]),  i<256, j<256
// ================================================================================
__global__ void __launch_bounds__(256) prep_w1(const float* __restrict__ W1) {
    __shared__ float tile[32 * 33];
    const int i = blockIdx.x, j0 = blockIdx.y * 32, n0 = blockIdx.z * 32;
    const int c = threadIdx.x & 31, r0 = threadIdx.x >> 5;
#pragma unroll
    for (int q = 0; q < 4; q++) {
        int jr = r0 + q * 8;
        size_t k = (size_t)i * NA + j0 + jr;
        tile[c * 33 + jr] = __uint_as_float(f2tf32(W1[k * NN + n0 + c]));
    }
    __syncthreads();
#pragma unroll
    for (int q = 0; q < 4; q++) {
        int nr = r0 + q * 8;
        g_W1t[(size_t)(n0 + nr) * KP2 + i * 264 + j0 + c] = tile[nr * 33 + c];
    }
}

// ================================================================================
// Main: split-K implicit GEMM on mma.sync tf32 (m16n8k8), ldmatrix + cp.async.
// CTA 128x128, 4 warps of 64x64. grid (32 M, 2 N, 8 splits).
// ================================================================================
__global__ void __launch_bounds__(128, 2) mma_main() {
    extern __shared__ __align__(1024) float smem[];
    // [0]:A0 16KB  [4096]:A1  [8192]:W0  [12288]:W1  (floats)
    const int tid = threadIdx.x;
    const int L   = tid & 31;
    const int wid = tid >> 5;
    const int wm  = wid & 1;    // M half (64)
    const int wn  = wid >> 1;   // N half (64)
    const int m0  = blockIdx.x * 128;
    const int n0  = blockIdx.y * 128;
    const int sp  = blockIdx.z;
    const int i0  = sp * 32;

    uint32_t sA[2] = { smem_u32(smem),        smem_u32(smem + 4096) };
    uint32_t sW[2] = { smem_u32(smem + 8192), smem_u32(smem + 12288) };

    // ldmatrix lane constants.
    // A frag: bit3 -> +8 rows, bit4 -> word half. B frag: bit4 -> +8 rows, bit3 -> word half.
    const int lsw  = L & 7;
    const int rowA = (L & 7) + ((L >> 3) & 1) * 8;
    const int hiA  = (L >> 4) & 1;
    const int rowB = (L & 7) + ((L >> 4) & 1) * 8;
    const int hiB  = (L >> 3) & 1;
    uint32_t swzA[4], swzB[4], aoff[4], boff[4];
#pragma unroll
    for (int q = 0; q < 4; q++) {
        swzA[q] = ((uint32_t)((2 * q + hiA) ^ lsw)) << 4;
        swzB[q] = ((uint32_t)((2 * q + hiB) ^ lsw)) << 4;
    }
#pragma unroll
    for (int f = 0; f < 4; f++) {
        aoff[f] = (uint32_t)(wm * 64 + f * 16 + rowA) * 128;
        boff[f] = (uint32_t)(wn * 64 + f * 16 + rowB) * 128;
    }

    float acc[4][8][4];
#pragma unroll
    for (int mf = 0; mf < 4; mf++)
#pragma unroll
        for (int nf = 0; nf < 8; nf++)
#pragma unroll
            for (int e = 0; e < 4; e++) acc[mf][nf][e] = 0.0f;

    // A-generation state: thread owns batch-row m = m0 + tid
    const float* aTb = g_aT + m0 + tid;                    // + i * B_SZ
    const float* bTb = g_bT + m0 + tid;                    // + j * B_SZ
    const uint32_t genO = (uint32_t)tid * 128;             // byte offset of my row
    const uint32_t gsw  = (uint32_t)(tid & 7);
    float breg[32];

    // W cp.async: thread owns weight-row n = n0 + tid
    const float* wRow = g_W1t + (size_t)(n0 + tid) * KP2;  // + i*264 + jc*32
    const uint32_t wO  = (uint32_t)tid * 128;
    const uint32_t wsw = (uint32_t)(tid & 7);

#define LDB(jc_) { _Pragma("unroll") \
    for (int e = 0; e < 32; e++) breg[e] = __ldg(bTb + (size_t)((jc_) * 32 + e) * B_SZ); }

#define GENA(buf_, av_) { const float av__ = (av_); _Pragma("unroll") \
    for (int w = 0; w < 8; w++) { \
        uint32_t v0 = f2tf32(av__ * breg[4*w+0]); \
        uint32_t v1 = f2tf32(av__ * breg[4*w+1]); \
        uint32_t v2 = f2tf32(av__ * breg[4*w+2]); \
        uint32_t v3 = f2tf32(av__ * breg[4*w+3]); \
        asm volatile("st.shared.v4.b32 [%0], {%1,%2,%3,%4};" \
            :: "r"(sA[buf_] + genO + (((uint32_t)w ^ gsw) << 4)), \
               "r"(v0), "r"(v1), "r"(v2), "r"(v3) : "memory"); } }

#define CPW(buf_, i_, jc_) { const float* src__ = wRow + (size_t)(i_) * 264 + (jc_) * 32; \
    _Pragma("unroll") \
    for (int w = 0; w < 8; w++) \
        cp16(sW[buf_] + wO + (((uint32_t)w ^ wsw) << 4), src__ + w * 4); \
    asm volatile("cp.async.commit_group;"); }

    // prologue: tile 0
    LDB(0);
    float av = __ldg(aTb + (size_t)i0 * B_SZ);
    GENA(0, av);
    CPW(0, i0, 0);
    float av_pf = __ldg(aTb + (size_t)(i0 + 1) * B_SZ);

    for (int T = 0; T < 256; T++) {
        const int buf = T & 1;
        asm volatile("cp.async.wait_group 0;");
        __syncthreads();

        if (T < 255) {
            const int Tn = T + 1, jcn = Tn >> 5, iin = Tn & 31;
            if (iin == 0) LDB(jcn);
            GENA(buf ^ 1, av_pf);
            CPW(buf ^ 1, i0 + iin, jcn);
            if (T < 254)
                av_pf = __ldg(aTb + (size_t)(i0 + ((T + 2) & 31)) * B_SZ);
        }

        // MMA on current buffer: 4 k-steps of 8
#pragma unroll
        for (int q = 0; q < 4; q++) {
            uint32_t afr[4][4], bfr[4][4];
#pragma unroll
            for (int mf = 0; mf < 4; mf++)
                ldsm4(sA[buf] + aoff[mf] + swzA[q], afr[mf]);
#pragma unroll
            for (int n2 = 0; n2 < 4; n2++)
                ldsm4(sW[buf] + boff[n2] + swzB[q], bfr[n2]);
#pragma unroll
            for (int mf = 0; mf < 4; mf++)
#pragma unroll
                for (int nf = 0; nf < 8; nf++)
                    mma_tf32(acc[mf][nf], afr[mf], &bfr[nf >> 1][(nf & 1) * 2]);
        }
    }

    // epilogue -> g_part[sp]
    float* base = g_part + (size_t)sp * B_SZ * NN;
#pragma unroll
    for (int mf = 0; mf < 4; mf++) {
        const int gm = m0 + wm * 64 + mf * 16 + (L >> 2);
#pragma unroll
        for (int nf = 0; nf < 8; nf++) {
            const int gn = n0 + wn * 64 + nf * 8 + 2 * (L & 3);
            float2 lo = { acc[mf][nf][0], acc[mf][nf][1] };
            float2 hi = { acc[mf][nf][2], acc[mf][nf][3] };
            *(float2*)(base + (size_t)gm * NN + gn)       = lo;
            *(float2*)(base + (size_t)(gm + 8) * NN + gn) = hi;
        }
    }
}

// ================================================================================
// Edge terms: j==256 for all i (K=257, incl i=256 where a=1), plus i==256 row
// (j<256). Combined K = 513. Writes g_part slot 8. ~1.08 GFLOP on FFMA2.
// ================================================================================
__global__ void __launch_bounds__(256) edge_kernel(const float* __restrict__ W1) {
    __shared__ float As[16][128];
    __shared__ float Wsh[16][136];
    const int m0 = blockIdx.x * 128, n0 = blockIdx.y * 128;
    const int t  = threadIdx.x;
    const int txn = t & 15, tym = t >> 4;   // 16x16 threads, 8x8 tile each

    unsigned long long acc[8][4];
#pragma unroll
    for (int n = 0; n < 8; n++)
#pragma unroll
        for (int p = 0; p < 4; p++) acc[n][p] = 0ull;

    for (int s = 0; s < 33; s++) {
#pragma unroll
        for (int it = 0; it < 8; it++) {
            int idx = t + it * 256;
            int kk = idx >> 7, m = idx & 127;
            int k = s * 16 + kk;
            float v = 0.0f;
            if (k < 256)      v = __ldg(g_aT + (size_t)k * B_SZ + m0 + m);
            else if (k == 256) v = 1.0f;
            else if (k < 513) v = __ldg(g_bT + (size_t)(k - 257) * B_SZ + m0 + m);
            As[kk][m] = v;
        }
#pragma unroll
        for (int it = 0; it < 8; it++) {
            int idx = t + it * 256;
            int kk = idx >> 7, n = idx & 127;
            int k = s * 16 + kk;
            float v = 0.0f;
            if (k < 513) {
                size_t row = (k < 257) ? ((size_t)k * NA + 256)
                                       : ((size_t)256 * NA + (k - 257));
                v = __ldg(W1 + row * NN + n0 + n);
            }
            Wsh[kk][n] = v;
        }
        __syncthreads();
#pragma unroll 4
        for (int kk = 0; kk < 16; kk++) {
            unsigned long long am[4];
#pragma unroll
            for (int p = 0; p < 4; p++)
                am[p] = *(const unsigned long long*)&As[kk][tym * 8 + 2 * p];
#pragma unroll
            for (int n = 0; n < 8; n++) {
                unsigned long long wp = pk1(Wsh[kk][txn * 8 + n]);
#pragma unroll
                for (int p = 0; p < 4; p++) acc[n][p] = ffma2(am[p], wp, acc[n][p]);
            }
        }
        __syncthreads();
    }

    float* base = g_part + (size_t)8 * B_SZ * NN;
#pragma unroll
    for (int p = 0; p < 4; p++) {
        const int gm = m0 + tym * 8 + 2 * p;
#pragma unroll
        for (int n = 0; n < 8; n++) {
            float x, y;
            upk(acc[n][p], x, y);
            base[(size_t)gm * NN + n0 + txn * 8 + n]       = x;
            base[(size_t)(gm + 1) * NN + n0 + txn * 8 + n] = y;
        }
    }
}

// ================================================================================
// Reduce 9 partial slots + b1 + relu -> h (smem), then layer2 FFMA2 + b2 + relu
// ================================================================================
__global__ void __launch_bounds__(256) reduce_l2(
    const float* __restrict__ b1, const float* __restrict__ W2,
    const float* __restrict__ b2, float* __restrict__ out) {
    __shared__ float h_t[256 * 34];  // h transposed: h_t[k][m], stride 34
    const int m0 = blockIdx.x * 32;
    const int n  = threadIdx.x;

    const float bb1 = __ldg(b1 + n);
#pragma unroll 4
    for (int q = 0; q < 32; q++) {
        float sum = bb1;
#pragma unroll
        for (int ss = 0; ss < NSLOT; ss++)
            sum += g_part[((size_t)ss * B_SZ + m0 + q) * NN + n];
        h_t[n * 34 + q] = fmaxf(sum, 0.0f);
    }
    __syncthreads();

    unsigned long long acc[16];
#pragma unroll
    for (int mp = 0; mp < 16; mp++) acc[mp] = 0ull;

#pragma unroll 4
    for (int k = 0; k < NN; k++) {
        const unsigned long long wp = pk1(__ldg(W2 + (size_t)k * NN + n));
        const float* hk = &h_t[k * 34];
#pragma unroll
        for (int mp = 0; mp < 16; mp++) {
            unsigned long long hv = *(const unsigned long long*)(hk + 2 * mp);
            acc[mp] = ffma2(hv, wp, acc[mp]);
        }
    }

    const float bb2 = __ldg(b2 + n);
#pragma unroll
    for (int mp = 0; mp < 16; mp++) {
        float x, y;
        upk(acc[mp], x, y);
        out[(size_t)(m0 + 2 * mp) * NN + n]     = fmaxf(x + bb2, 0.0f);
        out[(size_t)(m0 + 2 * mp + 1) * NN + n] = fmaxf(y + bb2, 0.0f);
    }
}

// ================================================================================
extern "C" void kernel_launch(void* const* d_in, const int* in_sizes, int n_in,
                              void* d_out, int out_size) {
    const float* inp1 = (const float*)d_in[0];
    const float* inp2 = (const float*)d_in[1];
    const float* W1   = (const float*)d_in[2];
    const float* b1   = (const float*)d_in[3];
    const float* W2   = (const float*)d_in[4];
    const float* b2   = (const float*)d_in[5];
    float* out = (float*)d_out;

    cudaFuncSetAttribute(mma_main, cudaFuncAttributeMaxDynamicSharedMemorySize, 65536);

    prep_inputs<<<dim3(128, 8, 2), 256>>>(inp1, inp2);
    prep_w1<<<dim3(256, 8, 8), 256>>>(W1);
    mma_main<<<dim3(32, 2, NSPLIT), 128, 65536>>>();
    edge_kernel<<<dim3(32, 2), 256>>>(W1);
    reduce_l2<<<B_SZ / 32, 256>>>(b1, W2, b2, out);
}

// round 7
// speedup vs baseline: 5.9824x; 1.7301x over previous
#include <cuda_runtime.h>
#include <cuda_fp16.h>
#include <cstdint>

#define B_SZ   4096
#define NN     256
#define NA     257
#define KP2H   65536        // W1t row length in halves: 256 i-blocks * 256
#define NSPLIT 8
#define NSLOT  9            // 8 mma splits + 1 edge slot

// ---------------- device-global scratch (no allocation allowed) ----------------
__device__ __align__(256) __half g_W1t[(size_t)NN * KP2H];          // 33.5 MB
__device__ __align__(256) float g_aT [(size_t)256 * B_SZ];          // 4 MB
__device__ __align__(256) float g_bT [(size_t)256 * B_SZ];          // 4 MB
__device__ __align__(256) float g_part[(size_t)NSLOT * B_SZ * NN];  // 37.7 MB

// ---------------- helpers ----------------
static __device__ __forceinline__ uint32_t smem_u32(const void* p) {
    uint32_t a;
    asm("{ .reg .u64 t; cvta.to.shared.u64 t, %1; cvt.u32.u64 %0, t; }" : "=r"(a) : "l"(p));
    return a;
}
static __device__ __forceinline__ void cp16(uint32_t s, const void* g) {
    asm volatile("cp.async.cg.shared.global [%0], [%1], 16;" :: "r"(s), "l"(g));
}
// pack (lo,hi) fp32 -> f16x2 (single final rounding, RN)
static __device__ __forceinline__ uint32_t pkh2(float lo, float hi) {
    uint32_t r;
    asm("cvt.rn.f16x2.f32 %0, %1, %2;" : "=r"(r) : "f"(hi), "f"(lo));
    return r;
}
static __device__ __forceinline__ unsigned long long pk1(float x) {
    unsigned long long r;
    asm("mov.b64 %0, {%1, %1};" : "=l"(r) : "f"(x));
    return r;
}
static __device__ __forceinline__ unsigned long long ffma2(
    unsigned long long a, unsigned long long b, unsigned long long c) {
    unsigned long long d;
    asm("fma.rn.f32x2 %0, %1, %2, %3;" : "=l"(d) : "l"(a), "l"(b), "l"(c));
    return d;
}
static __device__ __forceinline__ void upk(unsigned long long v, float& x, float& y) {
    asm("mov.b64 {%0, %1}, %2;" : "=f"(x), "=f"(y) : "l"(v));
}
static __device__ __forceinline__ void ldsm4(uint32_t addr, uint32_t r[4]) {
    asm volatile("ldmatrix.sync.aligned.m8n8.x4.shared.b16 {%0,%1,%2,%3}, [%4];"
                 : "=r"(r[0]), "=r"(r[1]), "=r"(r[2]), "=r"(r[3]) : "r"(addr));
}
static __device__ __forceinline__ void mma_f16(
    float d[4], const uint32_t a[4], const uint32_t b[2]) {
    asm volatile(
        "mma.sync.aligned.m16n8k16.row.col.f32.f16.f16.f32 "
        "{%0,%1,%2,%3}, {%4,%5,%6,%7}, {%8,%9}, {%0,%1,%2,%3};"
        : "+f"(d[0]), "+f"(d[1]), "+f"(d[2]), "+f"(d[3])
        : "r"(a[0]), "r"(a[1]), "r"(a[2]), "r"(a[3]), "r"(b[0]), "r"(b[1]));
}

// ================================================================================
// Pre-pass 1: transpose inp1 / inp2  ->  g_aT / g_bT  (fp32)
// ================================================================================
__global__ void __launch_bounds__(256) prep_inputs(
    const float* __restrict__ in1, const float* __restrict__ in2) {
    __shared__ float tile[32 * 33];
    const float* src = blockIdx.z ? in2 : in1;
    float* dst = blockIdx.z ? g_bT : g_aT;
    const int m0 = blockIdx.x * 32, c0 = blockIdx.y * 32;
    const int c = threadIdx.x & 31, r0 = threadIdx.x >> 5;
#pragma unroll
    for (int q = 0; q < 4; q++) {
        int r = r0 + q * 8;
        tile[c * 33 + r] = src[(size_t)(m0 + r) * 256 + c0 + c];
    }
    __syncthreads();
#pragma unroll
    for (int q = 0; q < 4; q++) {
        int rr = r0 + q * 8;
        dst[(size_t)(c0 + rr) * B_SZ + m0 + c] = tile[rr * 33 + c];
    }
}

// ================================================================================
// Pre-pass 2: W1t[n][i*256 + j] = fp16(W1[i*257+j][n]),  i<256, j<256
// ================================================================================
__global__ void __launch_bounds__(256) prep_w1(const float* __restrict__ W1) {
    __shared__ float tile[32 * 33];
    const int i = blockIdx.x, j0 = blockIdx.y * 32, n0 = blockIdx.z * 32;
    const int c = threadIdx.x & 31, r0 = threadIdx.x >> 5;
#pragma unroll
    for (int q = 0; q < 4; q++) {
        int jr = r0 + q * 8;
        size_t k = (size_t)i * NA + j0 + jr;
        tile[c * 33 + jr] = W1[k * NN + n0 + c];
    }
    __syncthreads();
#pragma unroll
    for (int q = 0; q < 4; q++) {
        int nr = r0 + q * 8;
        g_W1t[(size_t)(n0 + nr) * KP2H + (size_t)i * 256 + j0 + c] =
            __float2half_rn(tile[nr * 33 + c]);
    }
}

// ================================================================================
// Main: split-K implicit GEMM on mma.sync fp16 (m16n8k16), ldmatrix + cp.async.
// CTA 128x128, 4 warps of 64x64, K-tile 64 halves (128B rows, same swizzle as R5).
// grid (32 M, 2 N, 8 splits). Covers i in [0,256), j in [0,256).
// ================================================================================
__global__ void __launch_bounds__(128, 2) mma_main() {
    extern __shared__ __align__(1024) char smem[];
    const uint32_t sbase = smem_u32(smem);
    const uint32_t sA[2] = { sbase,         sbase + 16384 };
    const uint32_t sW[2] = { sbase + 32768, sbase + 49152 };

    const int tid = threadIdx.x;
    const int L   = tid & 31;
    const int wid = tid >> 5;
    const int wm  = wid & 1;
    const int wn  = wid >> 1;
    const int m0  = blockIdx.x * 128;
    const int n0  = blockIdx.y * 128;
    const int sp  = blockIdx.z;
    const int i0  = sp * 32;

    // ldsm lane constants (identical layout to validated tf32 version)
    const int lsw  = L & 7;
    const int rowA = (L & 7) + ((L >> 3) & 1) * 8;
    const int hiA  = (L >> 4) & 1;
    const int rowB = (L & 7) + ((L >> 4) & 1) * 8;
    const int hiB  = (L >> 3) & 1;
    uint32_t swzA[4], swzB[4], aoff[4], boff[4];
#pragma unroll
    for (int q = 0; q < 4; q++) {
        swzA[q] = ((uint32_t)((2 * q + hiA) ^ lsw)) << 4;
        swzB[q] = ((uint32_t)((2 * q + hiB) ^ lsw)) << 4;
    }
#pragma unroll
    for (int f = 0; f < 4; f++) {
        aoff[f] = (uint32_t)(wm * 64 + f * 16 + rowA) * 128;
        boff[f] = (uint32_t)(wn * 64 + f * 16 + rowB) * 128;
    }

    float acc[4][8][4];
#pragma unroll
    for (int mf = 0; mf < 4; mf++)
#pragma unroll
        for (int nf = 0; nf < 8; nf++)
#pragma unroll
            for (int e = 0; e < 4; e++) acc[mf][nf][e] = 0.0f;

    // A-gen: thread owns batch-row m = m0 + tid, all 64 k of the tile
    const float* aTb = g_aT + m0 + tid;
    const float* bTb = g_bT + m0 + tid;
    const uint32_t genO = (uint32_t)tid * 128;
    const uint32_t gsw  = (uint32_t)(tid & 7);
    float breg[64];  // b[myrow][jc*64 .. jc*64+63], fp32 (single-rounding precision)

    // W cp.async: thread owns weight-row n = n0 + tid
    const __half* wRow = g_W1t + (size_t)(n0 + tid) * KP2H;
    const uint32_t wO  = (uint32_t)tid * 128;
    const uint32_t wsw = (uint32_t)(tid & 7);

#define LDB(jc_) { _Pragma("unroll") \
    for (int e = 0; e < 64; e++) breg[e] = __ldg(bTb + (size_t)((jc_) * 64 + e) * B_SZ); }

#define GENA(buf_, av_) { const float av__ = (av_); _Pragma("unroll") \
    for (int w = 0; w < 8; w++) { \
        uint32_t v0 = pkh2(av__ * breg[8*w+0], av__ * breg[8*w+1]); \
        uint32_t v1 = pkh2(av__ * breg[8*w+2], av__ * breg[8*w+3]); \
        uint32_t v2 = pkh2(av__ * breg[8*w+4], av__ * breg[8*w+5]); \
        uint32_t v3 = pkh2(av__ * breg[8*w+6], av__ * breg[8*w+7]); \
        asm volatile("st.shared.v4.b32 [%0], {%1,%2,%3,%4};" \
            :: "r"(sA[buf_] + genO + (((uint32_t)w ^ gsw) << 4)), \
               "r"(v0), "r"(v1), "r"(v2), "r"(v3) : "memory"); } }

#define CPW(buf_, i_, jc_) { const __half* src__ = wRow + (size_t)(i_) * 256 + (jc_) * 64; \
    _Pragma("unroll") \
    for (int w = 0; w < 8; w++) \
        cp16(sW[buf_] + wO + (((uint32_t)w ^ wsw) << 4), src__ + w * 8); \
    asm volatile("cp.async.commit_group;"); }

    // prologue: tile 0 (jc=0, i=i0)
    LDB(0);
    float av = __ldg(aTb + (size_t)i0 * B_SZ);
    GENA(0, av);
    CPW(0, i0, 0);
    float av_pf = __ldg(aTb + (size_t)(i0 + 1) * B_SZ);

    const int NT = 128;  // 4 jc * 32 i
    for (int T = 0; T < NT; T++) {
        const int buf = T & 1;
        asm volatile("cp.async.wait_group 0;");
        __syncthreads();

        if (T < NT - 1) {
            const int Tn = T + 1, jcn = Tn >> 5, iin = Tn & 31;
            if (iin == 0) LDB(jcn);
            GENA(buf ^ 1, av_pf);
            CPW(buf ^ 1, i0 + iin, jcn);
            if (T < NT - 2)
                av_pf = __ldg(aTb + (size_t)(i0 + ((T + 2) & 31)) * B_SZ);
        }

        // MMA on current buffer: 4 k-steps of 16
#pragma unroll
        for (int q = 0; q < 4; q++) {
            uint32_t afr[4][4], bfr[4][4];
#pragma unroll
            for (int mf = 0; mf < 4; mf++)
                ldsm4(sA[buf] + aoff[mf] + swzA[q], afr[mf]);
#pragma unroll
            for (int n2 = 0; n2 < 4; n2++)
                ldsm4(sW[buf] + boff[n2] + swzB[q], bfr[n2]);
#pragma unroll
            for (int mf = 0; mf < 4; mf++)
#pragma unroll
                for (int nf = 0; nf < 8; nf++)
                    mma_f16(acc[mf][nf], afr[mf], &bfr[nf >> 1][(nf & 1) * 2]);
        }
    }

    // epilogue -> g_part[sp]
    float* base = g_part + (size_t)sp * B_SZ * NN;
#pragma unroll
    for (int mf = 0; mf < 4; mf++) {
        const int gm = m0 + wm * 64 + mf * 16 + (L >> 2);
#pragma unroll
        for (int nf = 0; nf < 8; nf++) {
            const int gn = n0 + wn * 64 + nf * 8 + 2 * (L & 3);
            float2 lo = { acc[mf][nf][0], acc[mf][nf][1] };
            float2 hi = { acc[mf][nf][2], acc[mf][nf][3] };
            *(float2*)(base + (size_t)gm * NN + gn)       = lo;
            *(float2*)(base + (size_t)(gm + 8) * NN + gn) = hi;
        }
    }
}

// ================================================================================
// Edge terms (fp32, exact): K = 513 = {j=256 for i in [0,256]} ∪ {i=256, j<256}
// Re-tiled 64x64, grid (64,4) = 256 CTAs, 4x4 per thread.  Writes slot 8.
// ================================================================================
__global__ void __launch_bounds__(256) edge_kernel(const float* __restrict__ W1) {
    __shared__ float As[32][64];
    __shared__ float Ws[32][68];
    const int m0 = blockIdx.x * 64, n0 = blockIdx.y * 64;
    const int t  = threadIdx.x;
    const int tx = t & 15, ty = t >> 4;

    float acc[4][4];
#pragma unroll
    for (int r = 0; r < 4; r++)
#pragma unroll
        for (int c = 0; c < 4; c++) acc[r][c] = 0.0f;

    for (int s = 0; s < 17; s++) {  // 17*32 = 544 >= 513, zero-padded
#pragma unroll
        for (int it = 0; it < 8; it++) {
            int idx = t + it * 256;
            int kk = idx >> 6, m = idx & 63;
            int k = s * 32 + kk;
            float v = 0.0f;
            if (k < 256)       v = __ldg(g_aT + (size_t)k * B_SZ + m0 + m);
            else if (k == 256) v = 1.0f;
            else if (k < 513)  v = __ldg(g_bT + (size_t)(k - 257) * B_SZ + m0 + m);
            As[kk][m] = v;
        }
#pragma unroll
        for (int it = 0; it < 8; it++) {
            int idx = t + it * 256;
            int kk = idx >> 6, n = idx & 63;
            int k = s * 32 + kk;
            float v = 0.0f;
            if (k <= 256)     v = __ldg(W1 + ((size_t)k * NA + 256) * NN + n0 + n);
            else if (k < 513) v = __ldg(W1 + ((size_t)256 * NA + (k - 257)) * NN + n0 + n);
            Ws[kk][n] = v;
        }
        __syncthreads();
#pragma unroll 8
        for (int k = 0; k < 32; k++) {
            float4 a4 = *(const float4*)&As[k][ty * 4];
            float4 w4 = *(const float4*)&Ws[k][tx * 4];
            const float ar[4] = { a4.x, a4.y, a4.z, a4.w };
            const float wr[4] = { w4.x, w4.y, w4.z, w4.w };
#pragma unroll
            for (int r = 0; r < 4; r++)
#pragma unroll
                for (int c = 0; c < 4; c++)
                    acc[r][c] = fmaf(ar[r], wr[c], acc[r][c]);
        }
        __syncthreads();
    }

    float* base = g_part + (size_t)8 * B_SZ * NN;
#pragma unroll
    for (int r = 0; r < 4; r++) {
        float4 v = { acc[r][0], acc[r][1], acc[r][2], acc[r][3] };
        *(float4*)(base + (size_t)(m0 + ty * 4 + r) * NN + n0 + tx * 4) = v;
    }
}

// ================================================================================
// Reduce 9 partial slots + b1 + relu -> h (smem), then layer2 FFMA2 + b2 + relu
// ================================================================================
__global__ void __launch_bounds__(256) reduce_l2(
    const float* __restrict__ b1, const float* __restrict__ W2,
    const float* __restrict__ b2, float* __restrict__ out) {
    __shared__ float h_t[256 * 34];  // h transposed: h_t[k][m], stride 34
    const int m0 = blockIdx.x * 32;
    const int n  = threadIdx.x;

    const float bb1 = __ldg(b1 + n);
#pragma unroll 4
    for (int q = 0; q < 32; q++) {
        float sum = bb1;
#pragma unroll
        for (int ss = 0; ss < NSLOT; ss++)
            sum += g_part[((size_t)ss * B_SZ + m0 + q) * NN + n];
        h_t[n * 34 + q] = fmaxf(sum, 0.0f);
    }
    __syncthreads();

    unsigned long long acc[16];
#pragma unroll
    for (int mp = 0; mp < 16; mp++) acc[mp] = 0ull;

#pragma unroll 4
    for (int k = 0; k < NN; k++) {
        const unsigned long long wp = pk1(__ldg(W2 + (size_t)k * NN + n));
        const float* hk = &h_t[k * 34];
#pragma unroll
        for (int mp = 0; mp < 16; mp++) {
            unsigned long long hv = *(const unsigned long long*)(hk + 2 * mp);
            acc[mp] = ffma2(hv, wp, acc[mp]);
        }
    }

    const float bb2 = __ldg(b2 + n);
#pragma unroll
    for (int mp = 0; mp < 16; mp++) {
        float x, y;
        upk(acc[mp], x, y);
        out[(size_t)(m0 + 2 * mp) * NN + n]     = fmaxf(x + bb2, 0.0f);
        out[(size_t)(m0 + 2 * mp + 1) * NN + n] = fmaxf(y + bb2, 0.0f);
    }
}

// ================================================================================
extern "C" void kernel_launch(void* const* d_in, const int* in_sizes, int n_in,
                              void* d_out, int out_size) {
    const float* inp1 = (const float*)d_in[0];
    const float* inp2 = (const float*)d_in[1];
    const float* W1   = (const float*)d_in[2];
    const float* b1   = (const float*)d_in[3];
    const float* W2   = (const float*)d_in[4];
    const float* b2   = (const float*)d_in[5];
    float* out = (float*)d_out;

    cudaFuncSetAttribute(mma_main, cudaFuncAttributeMaxDynamicSharedMemorySize, 65536);

    prep_inputs<<<dim3(128, 8, 2), 256>>>(inp1, inp2);
    prep_w1<<<dim3(256, 8, 8), 256>>>(W1);
    mma_main<<<dim3(32, 2, NSPLIT), 128, 65536>>>();
    edge_kernel<<<dim3(64, 4), 256>>>(W1);
    reduce_l2<<<B_SZ / 32, 256>>>(b1, W2, b2, out);
}

// round 8
// speedup vs baseline: 6.9686x; 1.1649x over previous
#include <cuda_runtime.h>
#include <cuda_fp16.h>
#include <cstdint>

#define B_SZ   4096
#define NN     256
#define NA     257
#define KP2H   65536        // W1t row length in halves: 256 i-blocks * 256
#define NSPLIT 8
#define NSLOT  8            // 8 mma splits (edge folded into the splits)

// ---------------- device-global scratch (no allocation allowed) ----------------
__device__ __align__(256) __half g_W1t[(size_t)NN * KP2H];          // 33.5 MB
__device__ __align__(256) __half g_W1e[(size_t)NN * 512];           // 256 KB edge weights
__device__ __align__(256) float g_aT [(size_t)256 * B_SZ];          // 4 MB
__device__ __align__(256) float g_bT [(size_t)256 * B_SZ];          // 4 MB
__device__ __align__(256) float g_part[(size_t)NSLOT * B_SZ * NN];  // 33.5 MB

// ---------------- helpers ----------------
static __device__ __forceinline__ uint32_t smem_u32(const void* p) {
    uint32_t a;
    asm("{ .reg .u64 t; cvta.to.shared.u64 t, %1; cvt.u32.u64 %0, t; }" : "=r"(a) : "l"(p));
    return a;
}
static __device__ __forceinline__ void cp16(uint32_t s, const void* g) {
    asm volatile("cp.async.cg.shared.global [%0], [%1], 16;" :: "r"(s), "l"(g));
}
// pack (lo,hi) fp32 -> f16x2 (single final rounding, RN)
static __device__ __forceinline__ uint32_t pkh2(float lo, float hi) {
    uint32_t r;
    asm("cvt.rn.f16x2.f32 %0, %1, %2;" : "=r"(r) : "f"(hi), "f"(lo));
    return r;
}
static __device__ __forceinline__ unsigned long long pk1(float x) {
    unsigned long long r;
    asm("mov.b64 %0, {%1, %1};" : "=l"(r) : "f"(x));
    return r;
}
static __device__ __forceinline__ unsigned long long ffma2(
    unsigned long long a, unsigned long long b, unsigned long long c) {
    unsigned long long d;
    asm("fma.rn.f32x2 %0, %1, %2, %3;" : "=l"(d) : "l"(a), "l"(b), "l"(c));
    return d;
}
static __device__ __forceinline__ void upk(unsigned long long v, float& x, float& y) {
    asm("mov.b64 {%0, %1}, %2;" : "=f"(x), "=f"(y) : "l"(v));
}
static __device__ __forceinline__ void ldsm4(uint32_t addr, uint32_t r[4]) {
    asm volatile("ldmatrix.sync.aligned.m8n8.x4.shared.b16 {%0,%1,%2,%3}, [%4];"
                 : "=r"(r[0]), "=r"(r[1]), "=r"(r[2]), "=r"(r[3]) : "r"(addr));
}
static __device__ __forceinline__ void mma_f16(
    float d[4], const uint32_t a[4], const uint32_t b[2]) {
    asm volatile(
        "mma.sync.aligned.m16n8k16.row.col.f32.f16.f16.f32 "
        "{%0,%1,%2,%3}, {%4,%5,%6,%7}, {%8,%9}, {%0,%1,%2,%3};"
        : "+f"(d[0]), "+f"(d[1]), "+f"(d[2]), "+f"(d[3])
        : "r"(a[0]), "r"(a[1]), "r"(a[2]), "r"(a[3]), "r"(b[0]), "r"(b[1]));
}

// ================================================================================
// Pre-pass 1: transpose inp1 / inp2  ->  g_aT / g_bT  (fp32)
// ================================================================================
__global__ void __launch_bounds__(256) prep_inputs(
    const float* __restrict__ in1, const float* __restrict__ in2) {
    __shared__ float tile[32 * 33];
    const float* src = blockIdx.z ? in2 : in1;
    float* dst = blockIdx.z ? g_bT : g_aT;
    const int m0 = blockIdx.x * 32, c0 = blockIdx.y * 32;
    const int c = threadIdx.x & 31, r0 = threadIdx.x >> 5;
#pragma unroll
    for (int q = 0; q < 4; q++) {
        int r = r0 + q * 8;
        tile[c * 33 + r] = src[(size_t)(m0 + r) * 256 + c0 + c];
    }
    __syncthreads();
#pragma unroll
    for (int q = 0; q < 4; q++) {
        int rr = r0 + q * 8;
        dst[(size_t)(c0 + rr) * B_SZ + m0 + c] = tile[rr * 33 + c];
    }
}

// ================================================================================
// Pre-pass 2: W1t[n][i*256 + j] = fp16(W1[i*257+j][n]),  i<256, j<256
// ================================================================================
__global__ void __launch_bounds__(256) prep_w1(const float* __restrict__ W1) {
    __shared__ float tile[32 * 33];
    const int i = blockIdx.x, j0 = blockIdx.y * 32, n0 = blockIdx.z * 32;
    const int c = threadIdx.x & 31, r0 = threadIdx.x >> 5;
#pragma unroll
    for (int q = 0; q < 4; q++) {
        int jr = r0 + q * 8;
        size_t k = (size_t)i * NA + j0 + jr;
        tile[c * 33 + jr] = W1[k * NN + n0 + c];
    }
    __syncthreads();
#pragma unroll
    for (int q = 0; q < 4; q++) {
        int nr = r0 + q * 8;
        g_W1t[(size_t)(n0 + nr) * KP2H + (size_t)i * 256 + j0 + c] =
            __float2half_rn(tile[nr * 33 + c]);
    }
}

// ================================================================================
// Pre-pass 3: edge weights. ke<257 -> W1 row ke*257+256 ; 257<=ke<512 -> row
// 65792+(ke-257).  g_W1e[n][ke] = fp16(W1[row(ke)][n]).
// ================================================================================
__global__ void __launch_bounds__(256) prep_w1e(const float* __restrict__ W1) {
    __shared__ float tile[32 * 33];
    const int k0 = blockIdx.x * 32, n0 = blockIdx.y * 32;
    const int c = threadIdx.x & 31, r0 = threadIdx.x >> 5;
#pragma unroll
    for (int q = 0; q < 4; q++) {
        int kr = r0 + q * 8;
        int ke = k0 + kr;
        size_t row = (ke < 257) ? ((size_t)ke * NA + 256)
                                : ((size_t)256 * NA + (ke - 257));
        tile[c * 33 + kr] = W1[row * NN + n0 + c];
    }
    __syncthreads();
#pragma unroll
    for (int q = 0; q < 4; q++) {
        int nr = r0 + q * 8;
        g_W1e[(size_t)(n0 + nr) * 512 + k0 + c] = __float2half_rn(tile[nr * 33 + c]);
    }
}

// ================================================================================
// Main: split-K implicit GEMM on mma.sync fp16 (m16n8k16), ldmatrix + cp.async.
// CTA 128x128, 4 warps of 64x64, K-tile 64 halves. grid (32 M, 2 N, 8 splits).
// Tiles 0..127: i in [i0,i0+32), j in [0,256). Tile 128: 64 edge columns
// (ke = sp*64 .. sp*64+63 of the 513-column edge set).
// ================================================================================
__global__ void __launch_bounds__(128, 2) mma_main() {
    extern __shared__ __align__(1024) char smem[];
    const uint32_t sbase = smem_u32(smem);
    const uint32_t sA[2] = { sbase,         sbase + 16384 };
    const uint32_t sW[2] = { sbase + 32768, sbase + 49152 };

    const int tid = threadIdx.x;
    const int L   = tid & 31;
    const int wid = tid >> 5;
    const int wm  = wid & 1;
    const int wn  = wid >> 1;
    const int m0  = blockIdx.x * 128;
    const int n0  = blockIdx.y * 128;
    const int sp  = blockIdx.z;
    const int i0  = sp * 32;

    // ldsm lane constants
    const int lsw  = L & 7;
    const int rowA = (L & 7) + ((L >> 3) & 1) * 8;
    const int hiA  = (L >> 4) & 1;
    const int rowB = (L & 7) + ((L >> 4) & 1) * 8;
    const int hiB  = (L >> 3) & 1;
    uint32_t swzA[4], swzB[4], aoff[4], boff[4];
#pragma unroll
    for (int q = 0; q < 4; q++) {
        swzA[q] = ((uint32_t)((2 * q + hiA) ^ lsw)) << 4;
        swzB[q] = ((uint32_t)((2 * q + hiB) ^ lsw)) << 4;
    }
#pragma unroll
    for (int f = 0; f < 4; f++) {
        aoff[f] = (uint32_t)(wm * 64 + f * 16 + rowA) * 128;
        boff[f] = (uint32_t)(wn * 64 + f * 16 + rowB) * 128;
    }

    float acc[4][8][4];
#pragma unroll
    for (int mf = 0; mf < 4; mf++)
#pragma unroll
        for (int nf = 0; nf < 8; nf++)
#pragma unroll
            for (int e = 0; e < 4; e++) acc[mf][nf][e] = 0.0f;

    // A-gen: thread owns batch-row m = m0 + tid
    const float* aTb = g_aT + m0 + tid;
    const float* bTb = g_bT + m0 + tid;
    const uint32_t genO = (uint32_t)tid * 128;
    const uint32_t gsw  = (uint32_t)(tid & 7);
    float breg[64];

    // W cp.async: thread owns weight-row n = n0 + tid
    const __half* wRow = g_W1t + (size_t)(n0 + tid) * KP2H;
    const __half* eRow = g_W1e + (size_t)(n0 + tid) * 512 + sp * 64;
    const uint32_t wO  = (uint32_t)tid * 128;
    const uint32_t wsw = (uint32_t)(tid & 7);

#define LDB(jc_) { _Pragma("unroll") \
    for (int e = 0; e < 64; e++) breg[e] = __ldg(bTb + (size_t)((jc_) * 64 + e) * B_SZ); }

#define GENA(buf_, av_) { const float av__ = (av_); _Pragma("unroll") \
    for (int w = 0; w < 8; w++) { \
        uint32_t v0 = pkh2(av__ * breg[8*w+0], av__ * breg[8*w+1]); \
        uint32_t v1 = pkh2(av__ * breg[8*w+2], av__ * breg[8*w+3]); \
        uint32_t v2 = pkh2(av__ * breg[8*w+4], av__ * breg[8*w+5]); \
        uint32_t v3 = pkh2(av__ * breg[8*w+6], av__ * breg[8*w+7]); \
        asm volatile("st.shared.v4.b32 [%0], {%1,%2,%3,%4};" \
            :: "r"(sA[buf_] + genO + (((uint32_t)w ^ gsw) << 4)), \
               "r"(v0), "r"(v1), "r"(v2), "r"(v3) : "memory"); } }

// Edge-tile A: A[m,e] = a[m,ke] (ke<256), 1 (ke==256), b[m,ke-257] (ke>256)
#define GENE(buf_) { _Pragma("unroll") \
    for (int w = 0; w < 8; w++) { \
        float v[8]; \
        _Pragma("unroll") \
        for (int r = 0; r < 8; r++) { \
            const int ke = sp * 64 + w * 8 + r; \
            float x; \
            if (ke < 256)       x = __ldg(aTb + (size_t)ke * B_SZ); \
            else if (ke == 256) x = 1.0f; \
            else                x = __ldg(bTb + (size_t)(ke - 257) * B_SZ); \
            v[r] = x; } \
        uint32_t p0 = pkh2(v[0], v[1]), p1 = pkh2(v[2], v[3]); \
        uint32_t p2 = pkh2(v[4], v[5]), p3 = pkh2(v[6], v[7]); \
        asm volatile("st.shared.v4.b32 [%0], {%1,%2,%3,%4};" \
            :: "r"(sA[buf_] + genO + (((uint32_t)w ^ gsw) << 4)), \
               "r"(p0), "r"(p1), "r"(p2), "r"(p3) : "memory"); } }

#define CPW(buf_, i_, jc_) { const __half* src__ = wRow + (size_t)(i_) * 256 + (jc_) * 64; \
    _Pragma("unroll") \
    for (int w = 0; w < 8; w++) \
        cp16(sW[buf_] + wO + (((uint32_t)w ^ wsw) << 4), src__ + w * 8); \
    asm volatile("cp.async.commit_group;"); }

#define CPWE(buf_) { _Pragma("unroll") \
    for (int w = 0; w < 8; w++) \
        cp16(sW[buf_] + wO + (((uint32_t)w ^ wsw) << 4), eRow + w * 8); \
    asm volatile("cp.async.commit_group;"); }

    // prologue: tile 0 (jc=0, i=i0)
    LDB(0);
    float av = __ldg(aTb + (size_t)i0 * B_SZ);
    GENA(0, av);
    CPW(0, i0, 0);
    float av_pf = __ldg(aTb + (size_t)(i0 + 1) * B_SZ);

    const int NT = 129;  // 4 jc * 32 i  + 1 edge tile
    for (int T = 0; T < NT; T++) {
        const int buf = T & 1;
        asm volatile("cp.async.wait_group 0;");
        __syncthreads();

        if (T < NT - 1) {
            const int Tn = T + 1;
            if (Tn == 128) {
                GENE(buf ^ 1);
                CPWE(buf ^ 1);
            } else {
                const int jcn = Tn >> 5, iin = Tn & 31;
                if (iin == 0) LDB(jcn);
                GENA(buf ^ 1, av_pf);
                CPW(buf ^ 1, i0 + iin, jcn);
                if (T < 126)
                    av_pf = __ldg(aTb + (size_t)(i0 + ((T + 2) & 31)) * B_SZ);
            }
        }

        // MMA on current buffer: 4 k-steps of 16
#pragma unroll
        for (int q = 0; q < 4; q++) {
            uint32_t afr[4][4], bfr[4][4];
#pragma unroll
            for (int mf = 0; mf < 4; mf++)
                ldsm4(sA[buf] + aoff[mf] + swzA[q], afr[mf]);
#pragma unroll
            for (int n2 = 0; n2 < 4; n2++)
                ldsm4(sW[buf] + boff[n2] + swzB[q], bfr[n2]);
#pragma unroll
            for (int mf = 0; mf < 4; mf++)
#pragma unroll
                for (int nf = 0; nf < 8; nf++)
                    mma_f16(acc[mf][nf], afr[mf], &bfr[nf >> 1][(nf & 1) * 2]);
        }
    }

    // epilogue -> g_part[sp]
    float* base = g_part + (size_t)sp * B_SZ * NN;
#pragma unroll
    for (int mf = 0; mf < 4; mf++) {
        const int gm = m0 + wm * 64 + mf * 16 + (L >> 2);
#pragma unroll
        for (int nf = 0; nf < 8; nf++) {
            const int gn = n0 + wn * 64 + nf * 8 + 2 * (L & 3);
            float2 lo = { acc[mf][nf][0], acc[mf][nf][1] };
            float2 hi = { acc[mf][nf][2], acc[mf][nf][3] };
            *(float2*)(base + (size_t)gm * NN + gn)       = lo;
            *(float2*)(base + (size_t)(gm + 8) * NN + gn) = hi;
        }
    }
}

// ================================================================================
// Reduce 8 partial slots + leftover edge column (ke=512 -> i=256,j=255) + b1 +
// relu -> h (smem), then layer2 FFMA2 + b2 + relu
// ================================================================================
__global__ void __launch_bounds__(256) reduce_l2(
    const float* __restrict__ W1, const float* __restrict__ b1,
    const float* __restrict__ W2, const float* __restrict__ b2,
    float* __restrict__ out) {
    __shared__ float h_t[256 * 34];  // h transposed: h_t[k][m], stride 34
    const int m0 = blockIdx.x * 32;
    const int n  = threadIdx.x;

    const float bb1 = __ldg(b1 + n);
    // leftover edge term: fusion[m, 256*257+255] = b[m,255]; weight row 66047
    const float wlast = __ldg(W1 + (size_t)66047 * NN + n);
#pragma unroll 4
    for (int q = 0; q < 32; q++) {
        const float blast = __ldg(g_bT + (size_t)255 * B_SZ + m0 + q);
        float sum = fmaf(blast, wlast, bb1);
#pragma unroll
        for (int ss = 0; ss < NSLOT; ss++)
            sum += g_part[((size_t)ss * B_SZ + m0 + q) * NN + n];
        h_t[n * 34 + q] = fmaxf(sum, 0.0f);
    }
    __syncthreads();

    unsigned long long acc[16];
#pragma unroll
    for (int mp = 0; mp < 16; mp++) acc[mp] = 0ull;

#pragma unroll 4
    for (int k = 0; k < NN; k++) {
        const unsigned long long wp = pk1(__ldg(W2 + (size_t)k * NN + n));
        const float* hk = &h_t[k * 34];
#pragma unroll
        for (int mp = 0; mp < 16; mp++) {
            unsigned long long hv = *(const unsigned long long*)(hk + 2 * mp);
            acc[mp] = ffma2(hv, wp, acc[mp]);
        }
    }

    const float bb2 = __ldg(b2 + n);
#pragma unroll
    for (int mp = 0; mp < 16; mp++) {
        float x, y;
        upk(acc[mp], x, y);
        out[(size_t)(m0 + 2 * mp) * NN + n]     = fmaxf(x + bb2, 0.0f);
        out[(size_t)(m0 + 2 * mp + 1) * NN + n] = fmaxf(y + bb2, 0.0f);
    }
}

// ================================================================================
extern "C" void kernel_launch(void* const* d_in, const int* in_sizes, int n_in,
                              void* d_out, int out_size) {
    const float* inp1 = (const float*)d_in[0];
    const float* inp2 = (const float*)d_in[1];
    const float* W1   = (const float*)d_in[2];
    const float* b1   = (const float*)d_in[3];
    const float* W2   = (const float*)d_in[4];
    const float* b2   = (const float*)d_in[5];
    float* out = (float*)d_out;

    cudaFuncSetAttribute(mma_main, cudaFuncAttributeMaxDynamicSharedMemorySize, 65536);

    prep_inputs<<<dim3(128, 8, 2), 256>>>(inp1, inp2);
    prep_w1<<<dim3(256, 8, 8), 256>>>(W1);
    prep_w1e<<<dim3(16, 8), 256>>>(W1);
    mma_main<<<dim3(32, 2, NSPLIT), 128, 65536>>>();
    reduce_l2<<<B_SZ / 32, 256>>>(W1, b1, W2, b2, out);
}